// round 16
// baseline (speedup 1.0000x reference)
#include <cuda_runtime.h>
#include <cuda_fp16.h>
#include <cstdint>
#include <cstddef>

#define L_DIM 4096
#define D_DIM 150
#define DP    160            // padded N
#define BM    64
#define BK    32             // 2 k16 steps per chunk
#define SPLITK 4
#define KCHUNK (L_DIM / SPLITK)   // 1024
#define NCHUNK (KCHUNK / BK)      // 32
#define ASTRIDE 40           // halves per A smem row (80B: LDSM conflict-free)
#define BSTRIDE 40
#define OUT_ELEMS (L_DIM * D_DIM)   // 614400

#define ATILE (BM * ASTRIDE * 2)   // 5120 B
#define BTILE (DP * BSTRIDE * 2)   // 12800 B
// A double-buffered, B triple-buffered (R14-proven layout)
#define OFF_AHI(b) ((b) * ATILE)
#define OFF_ALO(b) (2 * ATILE + (b) * ATILE)
#define OFF_BHI(b) (4 * ATILE + (b) * BTILE)
#define OFF_BLO(b) (4 * ATILE + 3 * BTILE + (b) * BTILE)
#define SMEM_TOTAL (4 * ATILE + 6 * BTILE)   // 97280 B

__device__ float  g_s0[(size_t)SPLITK * L_DIM * DP];   // h_out partials
__device__ float  g_s1[(size_t)SPLITK * L_DIM * DP];   // h_in partials
__device__ __half g_hT_hi[(size_t)DP * L_DIM];         // [n][k] K-major
__device__ __half g_hT_lo[(size_t)DP * L_DIM];
__device__ unsigned g_cnt[2][L_DIM / BM];              // split-K arrival counters (zero-init)

#define MMA16816(c0,c1,c2,c3, a0,a1,a2,a3, b0,b1)                            \
    asm volatile("mma.sync.aligned.m16n8k16.row.col.f32.f16.f16.f32 "        \
                 "{%0,%1,%2,%3}, {%4,%5,%6,%7}, {%8,%9}, {%0,%1,%2,%3};"     \
                 : "+f"(c0), "+f"(c1), "+f"(c2), "+f"(c3)                    \
                 : "r"(a0), "r"(a1), "r"(a2), "r"(a3), "r"(b0), "r"(b1))

#define LDSM_X4(r0,r1,r2,r3, addr)                                           \
    asm volatile("ldmatrix.sync.aligned.m8n8.x4.shared.b16 {%0,%1,%2,%3}, [%4];" \
                 : "=r"(r0), "=r"(r1), "=r"(r2), "=r"(r3) : "r"(addr))

#define LDSM_X2(r0,r1, addr)                                                 \
    asm volatile("ldmatrix.sync.aligned.m8n8.x2.shared.b16 {%0,%1}, [%2];"   \
                 : "=r"(r0), "=r"(r1) : "r"(addr))

#define CPASYNC16(dst, src)                                                  \
    asm volatile("cp.async.cg.shared.global [%0], [%1], 16;" :: "r"(dst), "l"(src))
#define CPCOMMIT() asm volatile("cp.async.commit_group;")
#define CPWAIT0()  asm volatile("cp.async.wait_group 0;")
#define CPWAIT1()  asm volatile("cp.async.wait_group 1;")

__device__ __forceinline__ void f16_split(float v, __half& hi, __half& lo) {
    hi = __float2half_rn(v);
    lo = __float2half_rn(v - __half2float(hi));
}

// Coalesced transpose prep: h[k][n] -> g_hT_{hi,lo}[n][k], zero-pad n>=150.
__global__ void prep_h_kernel(const float* __restrict__ h) {
    __shared__ float tile[8][161];
    const int t  = threadIdx.x;
    const int k0 = blockIdx.x * 8;
    #pragma unroll
    for (int r = 0; r < 5; r++) {
        const int e  = t + 256 * r;        // 0..1279
        const int kk = e / DP;
        const int n  = e - kk * DP;
        tile[kk][n] = (n < D_DIM) ? h[(size_t)(k0 + kk) * D_DIM + n] : 0.0f;
    }
    __syncthreads();
    #pragma unroll
    for (int r = 0; r < 5; r++) {
        const int e  = t + 256 * r;
        const int n  = e >> 3;             // 0..159
        const int kk = e & 7;
        __half hi, lo;
        f16_split(tile[kk][n], hi, lo);
        const size_t o = (size_t)n * L_DIM + k0 + kk;
        g_hT_hi[o] = hi;
        g_hT_lo[o] = lo;
    }
}

// partial[split][m][d] = sum_{k in split} Aeff[m,k]*h[k,d]  via 3xFP16 mma.sync
// Last-arriving split CTA for each m-tile reduces all 4 slabs -> final output.
template <bool TRANS>
__device__ __forceinline__
void gemm_body(const float* __restrict__ adj, float* __restrict__ sc,
               float* __restrict__ dst, unsigned* __restrict__ cnt, char* smem)
{
    uint32_t sbase;
    asm("{ .reg .u64 t; cvta.to.shared.u64 t, %1; cvt.u32.u64 %0, t; }"
        : "=r"(sbase) : "l"(smem));

    const int tid  = threadIdx.x;
    const int wid  = tid >> 5;
    const int lane = tid & 31;
    const int wm   = wid & 1;         // 2 x 32 rows
    const int wn   = wid >> 1;        // 4 x 40 cols
    const int qid  = lane >> 2;
    const int qk   = lane & 3;

    const int mBase = blockIdx.x * BM;
    const int kBase = blockIdx.y * KCHUNK;

    const int a_row = ((lane >> 3) & 1) * 8 + (lane & 7);
    const int a_col = (lane >> 4) * 8;
    const int b_row = lane & 7;
    const int b_col = ((lane >> 3) & 1) * 8;
    const int b4_row = (lane & 7) + ((lane >> 4) << 3);
    const int b4_col = ((lane >> 3) & 1) << 3;

    float acc[2][5][4];
    #pragma unroll
    for (int i = 0; i < 2; i++)
        #pragma unroll
        for (int j = 0; j < 5; j++)
            #pragma unroll
            for (int t = 0; t < 4; t++)
                acc[i][j][t] = 0.0f;

    float rv[16];

    auto loadA = [&](int it) {
        const int k0 = kBase + it * BK;
        if constexpr (!TRANS) {
            const int s = tid & 15;
            #pragma unroll
            for (int r = 0; r < 4; r++) {
                const int row = (tid >> 4) + 16 * r;
                const float4 v = *reinterpret_cast<const float4*>(
                    adj + ((size_t)(mBase + row) * (2 * L_DIM) + (size_t)k0 * 2 + s * 4));
                rv[r * 4 + 0] = v.x; rv[r * 4 + 1] = v.y;
                rv[r * 4 + 2] = v.z; rv[r * 4 + 3] = v.w;
            }
        } else {
            const int m   = tid & 63;
            const int oct = tid >> 6;
            #pragma unroll
            for (int j = 0; j < 8; j++) {
                const float2 v = *reinterpret_cast<const float2*>(
                    adj + ((size_t)(k0 + oct * 8 + j) * (2 * L_DIM) + (size_t)(mBase + m) * 2));
                rv[2 * j]     = v.x;
                rv[2 * j + 1] = v.y;
            }
        }
    };

    auto storeA = [&](int buf) {
        char* ahi = smem + OFF_AHI(buf);
        char* alo = smem + OFF_ALO(buf);
        if constexpr (!TRANS) {
            const int s = tid & 15;
            #pragma unroll
            for (int r = 0; r < 4; r++) {
                const int row = (tid >> 4) + 16 * r;
                __half ph, pl, qh, ql;
                f16_split(rv[r * 4 + 0] + rv[r * 4 + 1], ph, pl);
                f16_split(rv[r * 4 + 2] + rv[r * 4 + 3], qh, ql);
                const int o = (row * ASTRIDE + 2 * s) * 2;
                *reinterpret_cast<__half2*>(ahi + o) = __halves2half2(ph, qh);
                *reinterpret_cast<__half2*>(alo + o) = __halves2half2(pl, ql);
            }
        } else {
            const int m   = tid & 63;
            const int oct = tid >> 6;
            __half hh[8], ll[8];
            #pragma unroll
            for (int j = 0; j < 8; j++)
                f16_split(rv[2 * j] + rv[2 * j + 1], hh[j], ll[j]);
            const int o = (m * ASTRIDE + oct * 8) * 2;
            *reinterpret_cast<uint4*>(ahi + o) = *reinterpret_cast<const uint4*>(hh);
            *reinterpret_cast<uint4*>(alo + o) = *reinterpret_cast<const uint4*>(ll);
        }
    };

    auto loadB = [&](int it, int buf) {
        const int k0 = kBase + it * BK;
        const uint32_t bhi = sbase + OFF_BHI(buf);
        const uint32_t blo = sbase + OFF_BLO(buf);
        #pragma unroll
        for (int r = 0; r < 5; r++) {
            const int idx = tid + 256 * r;
            const int half_sel = idx >= 640;
            const int i2 = half_sel ? idx - 640 : idx;
            const int n = i2 >> 2;
            const int s = i2 & 3;
            const __half* src = (half_sel ? g_hT_lo : g_hT_hi)
                                + (size_t)n * L_DIM + k0 + s * 8;
            const uint32_t dst2 = (half_sel ? blo : bhi) + (n * BSTRIDE + s * 8) * 2;
            CPASYNC16(dst2, src);
        }
    };

    auto compute = [&](int abuf, int bbuf) {
        const uint32_t aHi = sbase + OFF_AHI(abuf);
        const uint32_t aLo = sbase + OFF_ALO(abuf);
        const uint32_t bHi = sbase + OFF_BHI(bbuf);
        const uint32_t bLo = sbase + OFF_BLO(bbuf);
        #pragma unroll
        for (int ks = 0; ks < 2; ks++) {
            const int kb = ks * 16;

            uint32_t ah[2][4], al[2][4];
            #pragma unroll
            for (int am = 0; am < 2; am++) {
                const uint32_t off =
                    ((wm * 32 + am * 16 + a_row) * ASTRIDE + kb + a_col) * 2;
                LDSM_X4(ah[am][0], ah[am][1], ah[am][2], ah[am][3], aHi + off);
                LDSM_X4(al[am][0], al[am][1], al[am][2], al[am][3], aLo + off);
            }

            uint32_t bh[5][2], bl[5][2];
            #pragma unroll
            for (int p = 0; p < 2; p++) {        // atom pairs 0-3 via X4
                const uint32_t off =
                    ((wn * 40 + p * 16 + b4_row) * BSTRIDE + kb + b4_col) * 2;
                LDSM_X4(bh[2*p][0], bh[2*p][1], bh[2*p+1][0], bh[2*p+1][1], bHi + off);
                LDSM_X4(bl[2*p][0], bl[2*p][1], bl[2*p+1][0], bl[2*p+1][1], bLo + off);
            }
            {
                const uint32_t off =
                    ((wn * 40 + 4 * 8 + b_row) * BSTRIDE + kb + b_col) * 2;
                LDSM_X2(bh[4][0], bh[4][1], bHi + off);
                LDSM_X2(bl[4][0], bl[4][1], bLo + off);
            }

            #pragma unroll
            for (int am = 0; am < 2; am++)
                #pragma unroll
                for (int an = 0; an < 5; an++) {
                    float* c = acc[am][an];
                    MMA16816(c[0], c[1], c[2], c[3],
                             ah[am][0], ah[am][1], ah[am][2], ah[am][3],
                             bh[an][0], bh[an][1]);
                    MMA16816(c[0], c[1], c[2], c[3],
                             ah[am][0], ah[am][1], ah[am][2], ah[am][3],
                             bl[an][0], bl[an][1]);
                    MMA16816(c[0], c[1], c[2], c[3],
                             al[am][0], al[am][1], al[am][2], al[am][3],
                             bh[an][0], bh[an][1]);
                }
        }
    };

    // ---- prologue: 2 B tiles in flight, A tile 0 resident ----
    loadA(0);
    loadB(0, 0); CPCOMMIT();
    loadB(1, 1); CPCOMMIT();
    storeA(0);
    CPWAIT1();
    __syncthreads();

    // ---- mainloop: A 2-stage, B 3-stage (R14-proven ordering) ----
    for (int it = 0; it < NCHUNK; it++) {
        const int abuf = it & 1;
        const int bbuf = it % 3;
        if (it + 2 < NCHUNK) { loadB(it + 2, (it + 2) % 3); CPCOMMIT(); }
        if (it + 1 < NCHUNK) loadA(it + 1);
        compute(abuf, bbuf);
        if (it + 1 < NCHUNK) {
            storeA((it + 1) & 1);
            if (it + 2 < NCHUNK) CPWAIT1();
            else                 CPWAIT0();
        }
        __syncthreads();
    }

    // ---- epilogue: write partials ----
    float* sp = sc + (size_t)blockIdx.y * ((size_t)L_DIM * DP);
    #pragma unroll
    for (int am = 0; am < 2; am++) {
        const int row = mBase + wm * 32 + am * 16 + qid;
        #pragma unroll
        for (int an = 0; an < 5; an++) {
            const int col = wn * 40 + an * 8 + qk * 2;
            *reinterpret_cast<float2*>(sp + (size_t)row * DP + col) =
                make_float2(acc[am][an][0], acc[am][an][1]);
            *reinterpret_cast<float2*>(sp + (size_t)(row + 8) * DP + col) =
                make_float2(acc[am][an][2], acc[am][an][3]);
        }
    }

    // ---- split-K fixup: last-arriving CTA reduces all 4 slabs ----
    __syncthreads();                       // all partial stores issued
    unsigned* flag = reinterpret_cast<unsigned*>(smem);
    if (tid == 0) {
        __threadfence();                   // partials visible before arrival
        *flag = atomicAdd(cnt, 1u);
    }
    __syncthreads();
    if (*flag == SPLITK - 1) {
        __threadfence();                   // see other CTAs' partials
        for (int i = tid; i < BM * D_DIM; i += 256) {
            const int r = i / D_DIM;
            const int d = i - r * D_DIM;
            const size_t b = (size_t)(mBase + r) * DP + d;
            const float s = sc[b]
                          + sc[(size_t)1 * L_DIM * DP + b]
                          + sc[(size_t)2 * L_DIM * DP + b]
                          + sc[(size_t)3 * L_DIM * DP + b];
            dst[(size_t)(mBase + r) * D_DIM + d] = s;
        }
        __syncthreads();
        if (tid == 0) *cnt = 0;            // reset for next graph replay
    }
}

// Both orientations co-scheduled in one launch: blockIdx.z selects the body.
__global__ __launch_bounds__(256)
void gemm_fused_kernel(const float* __restrict__ adj,
                       float* __restrict__ s0, float* __restrict__ s1,
                       float* __restrict__ out)
{
    extern __shared__ __align__(16) char smem[];
    if (blockIdx.z == 0)   // h_out = A @ h -> out[second half]
        gemm_body<false>(adj, s0, out + (size_t)OUT_ELEMS,
                         &g_cnt[0][blockIdx.x], smem);
    else                   // h_in = A^T @ h -> out[first half]
        gemm_body<true>(adj, s1, out,
                        &g_cnt[1][blockIdx.x], smem);
}

extern "C" void kernel_launch(void* const* d_in, const int* in_sizes, int n_in,
                              void* d_out, int out_size)
{
    const float* adj = (const float*)d_in[0];   // [L, L, 2] fp32
    const float* h   = (const float*)d_in[1];   // [L, D]    fp32
    float* out = (float*)d_out;                 // [2, L, D] : h_in then h_out

    static bool attr_set = false;
    if (!attr_set) {
        cudaFuncSetAttribute(gemm_fused_kernel,
                             cudaFuncAttributeMaxDynamicSharedMemorySize, SMEM_TOTAL);
        attr_set = true;
    }

    float* s0; cudaGetSymbolAddress((void**)&s0, g_s0);
    float* s1; cudaGetSymbolAddress((void**)&s1, g_s1);

    prep_h_kernel<<<L_DIM / 8, 256>>>(h);

    const dim3 grid(L_DIM / BM, SPLITK, 2);            // 512 CTAs, both passes
    gemm_fused_kernel<<<grid, 256, SMEM_TOTAL>>>(adj, s0, s1, out);
}

// round 17
// speedup vs baseline: 1.1008x; 1.1008x over previous
#include <cuda_runtime.h>
#include <cuda_fp16.h>
#include <cstdint>
#include <cstddef>

#define L_DIM 4096
#define D_DIM 150
#define DP    160            // padded N
#define BM    64
#define BK    32             // 2 k16 steps per chunk
#define SPLITK 4
#define KCHUNK (L_DIM / SPLITK)   // 1024
#define NCHUNK (KCHUNK / BK)      // 32
#define ASTRIDE 40           // halves per A smem row (80B: LDSM conflict-free)
#define BSTRIDE 40
#define OUT_ELEMS (L_DIM * D_DIM)   // 614400

#define ATILE (BM * ASTRIDE * 2)   // 5120 B
#define BTILE (DP * BSTRIDE * 2)   // 12800 B
// A double-buffered, B triple-buffered (R14-proven layout)
#define OFF_AHI(b) ((b) * ATILE)
#define OFF_ALO(b) (2 * ATILE + (b) * ATILE)
#define OFF_BHI(b) (4 * ATILE + (b) * BTILE)
#define OFF_BLO(b) (4 * ATILE + 3 * BTILE + (b) * BTILE)
#define SMEM_TOTAL (4 * ATILE + 6 * BTILE)   // 97280 B

__device__ float  g_s0[(size_t)SPLITK * L_DIM * DP];   // h_out partials
__device__ float  g_s1[(size_t)SPLITK * L_DIM * DP];   // h_in partials
__device__ __half g_hT_hi[(size_t)DP * L_DIM];         // [n][k] K-major
__device__ __half g_hT_lo[(size_t)DP * L_DIM];

#define MMA16816(c0,c1,c2,c3, a0,a1,a2,a3, b0,b1)                            \
    asm volatile("mma.sync.aligned.m16n8k16.row.col.f32.f16.f16.f32 "        \
                 "{%0,%1,%2,%3}, {%4,%5,%6,%7}, {%8,%9}, {%0,%1,%2,%3};"     \
                 : "+f"(c0), "+f"(c1), "+f"(c2), "+f"(c3)                    \
                 : "r"(a0), "r"(a1), "r"(a2), "r"(a3), "r"(b0), "r"(b1))

#define LDSM_X4(r0,r1,r2,r3, addr)                                           \
    asm volatile("ldmatrix.sync.aligned.m8n8.x4.shared.b16 {%0,%1,%2,%3}, [%4];" \
                 : "=r"(r0), "=r"(r1), "=r"(r2), "=r"(r3) : "r"(addr))

#define LDSM_X2(r0,r1, addr)                                                 \
    asm volatile("ldmatrix.sync.aligned.m8n8.x2.shared.b16 {%0,%1}, [%2];"   \
                 : "=r"(r0), "=r"(r1) : "r"(addr))

#define CPASYNC16(dst, src)                                                  \
    asm volatile("cp.async.cg.shared.global [%0], [%1], 16;" :: "r"(dst), "l"(src))
#define CPCOMMIT() asm volatile("cp.async.commit_group;")
#define CPWAIT0()  asm volatile("cp.async.wait_group 0;")
#define CPWAIT1()  asm volatile("cp.async.wait_group 1;")

__device__ __forceinline__ void f16_split(float v, __half& hi, __half& lo) {
    hi = __float2half_rn(v);
    lo = __float2half_rn(v - __half2float(hi));
}

// Coalesced transpose prep: h[k][n] -> g_hT_{hi,lo}[n][k], zero-pad n>=150.
// Phase 2: one thread per n-column, vectorized 16B stores (values identical
// to the old scalar path).
__global__ void prep_h_kernel(const float* __restrict__ h) {
    __shared__ float tile[8][161];
    const int t  = threadIdx.x;
    const int k0 = blockIdx.x * 8;
    #pragma unroll
    for (int r = 0; r < 5; r++) {
        const int e  = t + 256 * r;        // 0..1279
        const int kk = e / DP;
        const int n  = e - kk * DP;
        tile[kk][n] = (n < D_DIM) ? h[(size_t)(k0 + kk) * D_DIM + n] : 0.0f;
    }
    __syncthreads();
    if (t < DP) {
        __half hh[8], ll[8];
        #pragma unroll
        for (int kk = 0; kk < 8; kk++)
            f16_split(tile[kk][t], hh[kk], ll[kk]);
        const size_t o = (size_t)t * L_DIM + k0;
        *reinterpret_cast<uint4*>(g_hT_hi + o) = *reinterpret_cast<const uint4*>(hh);
        *reinterpret_cast<uint4*>(g_hT_lo + o) = *reinterpret_cast<const uint4*>(ll);
    }
}

// partial[split][m][d] = sum_{k in split} Aeff[m,k]*h[k,d]  via 3xFP16 mma.sync
template <bool TRANS>
__device__ __forceinline__
void gemm_body(const float* __restrict__ adj, float* __restrict__ sc, char* smem)
{
    uint32_t sbase;
    asm("{ .reg .u64 t; cvta.to.shared.u64 t, %1; cvt.u32.u64 %0, t; }"
        : "=r"(sbase) : "l"(smem));

    const int tid  = threadIdx.x;
    const int wid  = tid >> 5;
    const int lane = tid & 31;
    const int wm   = wid & 1;         // 2 x 32 rows
    const int wn   = wid >> 1;        // 4 x 40 cols
    const int qid  = lane >> 2;
    const int qk   = lane & 3;

    const int mBase = blockIdx.x * BM;
    const int kBase = blockIdx.y * KCHUNK;

    const int a_row = ((lane >> 3) & 1) * 8 + (lane & 7);
    const int a_col = (lane >> 4) * 8;
    const int b_row = lane & 7;
    const int b_col = ((lane >> 3) & 1) * 8;
    const int b4_row = (lane & 7) + ((lane >> 4) << 3);
    const int b4_col = ((lane >> 3) & 1) << 3;

    float acc[2][5][4];
    #pragma unroll
    for (int i = 0; i < 2; i++)
        #pragma unroll
        for (int j = 0; j < 5; j++)
            #pragma unroll
            for (int t = 0; t < 4; t++)
                acc[i][j][t] = 0.0f;

    float rv[16];

    auto loadA = [&](int it) {
        const int k0 = kBase + it * BK;
        if constexpr (!TRANS) {
            const int s = tid & 15;
            #pragma unroll
            for (int r = 0; r < 4; r++) {
                const int row = (tid >> 4) + 16 * r;
                const float4 v = *reinterpret_cast<const float4*>(
                    adj + ((size_t)(mBase + row) * (2 * L_DIM) + (size_t)k0 * 2 + s * 4));
                rv[r * 4 + 0] = v.x; rv[r * 4 + 1] = v.y;
                rv[r * 4 + 2] = v.z; rv[r * 4 + 3] = v.w;
            }
        } else {
            const int m   = tid & 63;
            const int oct = tid >> 6;
            #pragma unroll
            for (int j = 0; j < 8; j++) {
                const float2 v = *reinterpret_cast<const float2*>(
                    adj + ((size_t)(k0 + oct * 8 + j) * (2 * L_DIM) + (size_t)(mBase + m) * 2));
                rv[2 * j]     = v.x;
                rv[2 * j + 1] = v.y;
            }
        }
    };

    auto storeA = [&](int buf) {
        char* ahi = smem + OFF_AHI(buf);
        char* alo = smem + OFF_ALO(buf);
        if constexpr (!TRANS) {
            const int s = tid & 15;
            #pragma unroll
            for (int r = 0; r < 4; r++) {
                const int row = (tid >> 4) + 16 * r;
                __half ph, pl, qh, ql;
                f16_split(rv[r * 4 + 0] + rv[r * 4 + 1], ph, pl);
                f16_split(rv[r * 4 + 2] + rv[r * 4 + 3], qh, ql);
                const int o = (row * ASTRIDE + 2 * s) * 2;
                *reinterpret_cast<__half2*>(ahi + o) = __halves2half2(ph, qh);
                *reinterpret_cast<__half2*>(alo + o) = __halves2half2(pl, ql);
            }
        } else {
            const int m   = tid & 63;
            const int oct = tid >> 6;
            __half hh[8], ll[8];
            #pragma unroll
            for (int j = 0; j < 8; j++)
                f16_split(rv[2 * j] + rv[2 * j + 1], hh[j], ll[j]);
            const int o = (m * ASTRIDE + oct * 8) * 2;
            *reinterpret_cast<uint4*>(ahi + o) = *reinterpret_cast<const uint4*>(hh);
            *reinterpret_cast<uint4*>(alo + o) = *reinterpret_cast<const uint4*>(ll);
        }
    };

    auto loadB = [&](int it, int buf) {
        const int k0 = kBase + it * BK;
        const uint32_t bhi = sbase + OFF_BHI(buf);
        const uint32_t blo = sbase + OFF_BLO(buf);
        #pragma unroll
        for (int r = 0; r < 5; r++) {
            const int idx = tid + 256 * r;
            const int half_sel = idx >= 640;
            const int i2 = half_sel ? idx - 640 : idx;
            const int n = i2 >> 2;
            const int s = i2 & 3;
            const __half* src = (half_sel ? g_hT_lo : g_hT_hi)
                                + (size_t)n * L_DIM + k0 + s * 8;
            const uint32_t dst = (half_sel ? blo : bhi) + (n * BSTRIDE + s * 8) * 2;
            CPASYNC16(dst, src);
        }
    };

    auto compute = [&](int abuf, int bbuf) {
        const uint32_t aHi = sbase + OFF_AHI(abuf);
        const uint32_t aLo = sbase + OFF_ALO(abuf);
        const uint32_t bHi = sbase + OFF_BHI(bbuf);
        const uint32_t bLo = sbase + OFF_BLO(bbuf);
        #pragma unroll
        for (int ks = 0; ks < 2; ks++) {
            const int kb = ks * 16;

            uint32_t ah[2][4], al[2][4];
            #pragma unroll
            for (int am = 0; am < 2; am++) {
                const uint32_t off =
                    ((wm * 32 + am * 16 + a_row) * ASTRIDE + kb + a_col) * 2;
                LDSM_X4(ah[am][0], ah[am][1], ah[am][2], ah[am][3], aHi + off);
                LDSM_X4(al[am][0], al[am][1], al[am][2], al[am][3], aLo + off);
            }

            uint32_t bh[5][2], bl[5][2];
            #pragma unroll
            for (int p = 0; p < 2; p++) {        // atom pairs 0-3 via X4
                const uint32_t off =
                    ((wn * 40 + p * 16 + b4_row) * BSTRIDE + kb + b4_col) * 2;
                LDSM_X4(bh[2*p][0], bh[2*p][1], bh[2*p+1][0], bh[2*p+1][1], bHi + off);
                LDSM_X4(bl[2*p][0], bl[2*p][1], bl[2*p+1][0], bl[2*p+1][1], bLo + off);
            }
            {
                const uint32_t off =
                    ((wn * 40 + 4 * 8 + b_row) * BSTRIDE + kb + b_col) * 2;
                LDSM_X2(bh[4][0], bh[4][1], bHi + off);
                LDSM_X2(bl[4][0], bl[4][1], bLo + off);
            }

            #pragma unroll
            for (int am = 0; am < 2; am++)
                #pragma unroll
                for (int an = 0; an < 5; an++) {
                    float* c = acc[am][an];
                    MMA16816(c[0], c[1], c[2], c[3],
                             ah[am][0], ah[am][1], ah[am][2], ah[am][3],
                             bh[an][0], bh[an][1]);
                    MMA16816(c[0], c[1], c[2], c[3],
                             ah[am][0], ah[am][1], ah[am][2], ah[am][3],
                             bl[an][0], bl[an][1]);
                    MMA16816(c[0], c[1], c[2], c[3],
                             al[am][0], al[am][1], al[am][2], al[am][3],
                             bh[an][0], bh[an][1]);
                }
        }
    };

    // ---- prologue: 2 B tiles in flight, A tile 0 resident ----
    loadA(0);
    loadB(0, 0); CPCOMMIT();
    loadB(1, 1); CPCOMMIT();
    storeA(0);
    CPWAIT1();
    __syncthreads();

    // ---- mainloop: A 2-stage, B 3-stage (R14-proven ordering) ----
    for (int it = 0; it < NCHUNK; it++) {
        const int abuf = it & 1;
        const int bbuf = it % 3;
        if (it + 2 < NCHUNK) { loadB(it + 2, (it + 2) % 3); CPCOMMIT(); }
        if (it + 1 < NCHUNK) loadA(it + 1);
        compute(abuf, bbuf);
        if (it + 1 < NCHUNK) {
            storeA((it + 1) & 1);
            if (it + 2 < NCHUNK) CPWAIT1();
            else                 CPWAIT0();
        }
        __syncthreads();
    }

    // ---- epilogue ----
    float* sp = sc + (size_t)blockIdx.y * ((size_t)L_DIM * DP);
    #pragma unroll
    for (int am = 0; am < 2; am++) {
        const int row = mBase + wm * 32 + am * 16 + qid;
        #pragma unroll
        for (int an = 0; an < 5; an++) {
            const int col = wn * 40 + an * 8 + qk * 2;
            *reinterpret_cast<float2*>(sp + (size_t)row * DP + col) =
                make_float2(acc[am][an][0], acc[am][an][1]);
            *reinterpret_cast<float2*>(sp + (size_t)(row + 8) * DP + col) =
                make_float2(acc[am][an][2], acc[am][an][3]);
        }
    }
}

// Both orientations co-scheduled in one launch: blockIdx.z selects the body.
__global__ __launch_bounds__(256)
void gemm_fused_kernel(const float* __restrict__ adj,
                       float* __restrict__ s0, float* __restrict__ s1)
{
    extern __shared__ __align__(16) char smem[];
    if (blockIdx.z == 0)
        gemm_body<false>(adj, s0, smem);   // h_out = A @ h
    else
        gemm_body<true>(adj, s1, smem);    // h_in  = A^T @ h
}

// Tail reduction in float2 (pairs never cross row boundaries since D_DIM even
// and pair starts are even). Same slab summation order -> bit-identical.
// out[0..OUT) = h_in from s1;  out[OUT..2*OUT) = h_out from s0
__global__ void reduce_both_kernel(const float* __restrict__ s0,
                                   const float* __restrict__ s1,
                                   float* __restrict__ out)
{
    const int p0 = blockIdx.x * 1024 + threadIdx.x;
    #pragma unroll
    for (int r = 0; r < 4; r++) {
        const int p   = p0 + 256 * r;      // pair index
        const int idx = p * 2;
        if (idx < 2 * OUT_ELEMS) {
            const int sel   = idx >= OUT_ELEMS;
            const int local = sel ? idx - OUT_ELEMS : idx;
            const float* src = sel ? s0 : s1;
            const int row = local / D_DIM;
            const int d   = local - row * D_DIM;       // even
            const size_t b = (size_t)row * DP + d;
            const float2 v0 = *reinterpret_cast<const float2*>(src + b);
            const float2 v1 = *reinterpret_cast<const float2*>(src + (size_t)1 * L_DIM * DP + b);
            const float2 v2 = *reinterpret_cast<const float2*>(src + (size_t)2 * L_DIM * DP + b);
            const float2 v3 = *reinterpret_cast<const float2*>(src + (size_t)3 * L_DIM * DP + b);
            float2 o;
            o.x = v0.x + v1.x + v2.x + v3.x;
            o.y = v0.y + v1.y + v2.y + v3.y;
            *reinterpret_cast<float2*>(out + idx) = o;
        }
    }
}

extern "C" void kernel_launch(void* const* d_in, const int* in_sizes, int n_in,
                              void* d_out, int out_size)
{
    const float* adj = (const float*)d_in[0];   // [L, L, 2] fp32
    const float* h   = (const float*)d_in[1];   // [L, D]    fp32
    float* out = (float*)d_out;                 // [2, L, D] : h_in then h_out

    static bool attr_set = false;
    if (!attr_set) {
        cudaFuncSetAttribute(gemm_fused_kernel,
                             cudaFuncAttributeMaxDynamicSharedMemorySize, SMEM_TOTAL);
        attr_set = true;
    }

    float* s0; cudaGetSymbolAddress((void**)&s0, g_s0);
    float* s1; cudaGetSymbolAddress((void**)&s1, g_s1);

    prep_h_kernel<<<L_DIM / 8, 256>>>(h);

    const dim3 grid(L_DIM / BM, SPLITK, 2);            // 512 CTAs, both passes
    gemm_fused_kernel<<<grid, 256, SMEM_TOTAL>>>(adj, s0, s1);

    const int red_blocks = (OUT_ELEMS + 1023) / 1024;  // 600 blocks, 1024 pairs each
    reduce_both_kernel<<<red_blocks, 256>>>(s0, s1, out);
}